// round 13
// baseline (speedup 1.0000x reference)
#include <cuda_runtime.h>
#include <cuda_bf16.h>

// P1 FEM evaluation on a structured 17x17 grid over [0,1]^2.
// Direct cell lookup replaces the reference's 512-triangle scan.
//
// Bitwise-faithful DECISION logic vs the JAX reference (validated R4-R12):
//  - x*16 is an exact exponent shift; dx = ux - floor(ux), dy = uy - floor(uy)
//    and e = dy - dx are EXACT in fp32.
//  - Reference's 6 triangle conditions collapse to: upper wins iff e > -TOL.
//  - Algebraic fold (R12, validated): upper_val - lower_val = -e*g with
//    g = w00+w11-w01-w10 per cell, so
//      val = w00 + (w10-w00)*dx + (w11-w10)*dy - max(e,0)*g
//    (tie-band difference <= 1e-10*|g|, far below the 1e-3 tolerance;
//     measured rel_err 9.1e-8)
//  - Interior grid-line points output 0 (`dead`); x==0 / y==0 edges survive.
//
// R13 (hypothesis: L1TEX-queue-inflated latency not covered by TLP; every
// prior config had <=66% occupancy):
//  - __launch_bounds__(256, 8) -> <=32 regs -> 8 blocks/SM, 64 warps,
//    ~100% theoretical occupancy
//  - thin threads: 4 points each (2 front-batched LDG.128, 1 STG.128),
//    2048 self-balancing blocks

static constexpr float TOLF = 1e-10f;

__device__ __forceinline__ float eval_point(float X, float Y,
                                            const float4* __restrict__ tab) {
    float ux = X * 16.0f;              // exact (power-of-2 scale)
    float uy = Y * 16.0f;
    float fx = floorf(ux);
    float fy = floorf(uy);

    float dx = ux - fx;                // exact
    float dy = uy - fy;                // exact
    float e  = dy - dx;                // exact

    // Interior grid line -> reference's strict bbox test fails everywhere.
    bool dead = ((dx == 0.0f) && (ux != 0.0f)) || ((dy == 0.0f) && (uy != 0.0f));

    int cell = (int)fmaf(fx, 16.0f, fy);   // i*16 + j, exact in fp32
    float4 q = tab[cell];              // (w00, b, c, g) - one LDS.128

    float emax = fmaxf(e, 0.0f);
    float val  = fmaf(q.y, dx, fmaf(q.z, dy, q.x));
    val = fmaf(-emax, q.w, val);

    return dead ? 0.0f : val;
}

__global__ void __launch_bounds__(256, 8)
p1_eval_kernel(const float4* __restrict__ x4,
               const float*  __restrict__ w,
               float4*       __restrict__ out4) {
    // Per-cell fold coefficients: (w00, w10-w00, w11-w10, w00+w11-w01-w10).
    __shared__ float4 tab[256];
    {
        int t = threadIdx.x;           // cell = i*16 + j
        int v = (t >> 4) * 17 + (t & 15);
        float w00 = w[v], w01 = w[v + 1], w10 = w[v + 17], w11 = w[v + 18];
        tab[t] = make_float4(w00, w10 - w00, w11 - w10,
                             (w00 + w11) - (w01 + w10));
    }
    __syncthreads();

    // Thin thread: 4 points = 2 input float4 (front-batched), 1 output float4.
    int o = blockIdx.x * 256 + threadIdx.x;    // output float4 index

    float4 a0 = x4[2 * o];
    float4 a1 = x4[2 * o + 1];

    float4 r;
    r.x = eval_point(a0.x, a0.y, tab);
    r.y = eval_point(a0.z, a0.w, tab);
    r.z = eval_point(a1.x, a1.y, tab);
    r.w = eval_point(a1.z, a1.w, tab);

    out4[o] = r;
}

extern "C" void kernel_launch(void* const* d_in, const int* in_sizes, int n_in,
                              void* d_out, int out_size) {
    // Identify inputs by element count: x = largest (4,194,304 floats),
    // weight = 289 floats.
    const float* x = nullptr;
    const float* w = nullptr;
    int max_sz = -1;
    for (int k = 0; k < n_in; k++) {
        if (in_sizes[k] == 289) w = (const float*)d_in[k];
        if (in_sizes[k] > max_sz) { max_sz = in_sizes[k]; x = (const float*)d_in[k]; }
    }

    // 2,097,152 points -> 524,288 output float4 -> 2048 blocks x 256 threads.
    p1_eval_kernel<<<2048, 256>>>((const float4*)x, w, (float4*)d_out);
}

// round 14
// speedup vs baseline: 1.0354x; 1.0354x over previous
#include <cuda_runtime.h>
#include <cuda_bf16.h>
#include <cuda_fp16.h>

// P1 FEM evaluation on a structured 17x17 grid over [0,1]^2.
// Direct cell lookup replaces the reference's 512-triangle scan.
//
// DECISION logic is exact fp32 and bitwise-faithful to the JAX reference
// (validated R4-R13):
//  - x*16 is an exact exponent shift; dx, dy, e = dy-dx are EXACT in fp32.
//  - Reference's 6 triangle conditions collapse to: upper wins iff e > -TOL;
//    algebraic fold val = w00 + b*dx + c*dy - max(e,0)*g with
//    b=w10-w00, c=w11-w10, g=w00+w11-w01-w10 (tie band error <= 1e-10*|g|).
//  - Interior grid-line points output 0 (`dead`); x==0 / y==0 edges survive.
//
// R14 change (L1TEX is the leading pipe at 48.8%; ~77% of its wavefronts are
// the random-cell table gather):
//  - table compressed to fp16: one 8-byte entry (w00,b,c,g) per cell ->
//    LDS.64 gather = 2 phases x ~2.7 conflicts (~5.4 wf) vs LDS.128's ~10
//  - value interpolation in fp32 after __half22float2 unpack; expected
//    rel_err ~2.5e-4 (norm-based metric, threshold 1e-3; decisions exact)
//  - config frozen at R13 (thin threads, 2048x256, <=32 regs, 8 blocks/SM)
//    so the table format is the only variable

static constexpr float TOLF = 1e-10f;

__device__ __forceinline__ float eval_point(float X, float Y,
                                            const __half2* __restrict__ tab) {
    float ux = X * 16.0f;              // exact (power-of-2 scale)
    float uy = Y * 16.0f;
    float fx = floorf(ux);
    float fy = floorf(uy);

    float dx = ux - fx;                // exact
    float dy = uy - fy;                // exact
    float e  = dy - dx;                // exact

    // Interior grid line -> reference's strict bbox test fails everywhere.
    bool dead = ((dx == 0.0f) && (ux != 0.0f)) || ((dy == 0.0f) && (uy != 0.0f));

    int cell = (int)fmaf(fx, 16.0f, fy);   // i*16 + j, exact in fp32

    // One LDS.64: {half2(w00,b), half2(c,g)}
    __half2 h01 = tab[2 * cell];
    __half2 h23 = tab[2 * cell + 1];
    float2 wb = __half22float2(h01);   // (w00, b)
    float2 cg = __half22float2(h23);   // (c, g)

    float emax = fmaxf(e, 0.0f);
    float val  = fmaf(wb.y, dx, fmaf(cg.x, dy, wb.x));
    val = fmaf(-emax, cg.y, val);

    return dead ? 0.0f : val;
}

__global__ void __launch_bounds__(256, 8)
p1_eval_kernel(const float4* __restrict__ x4,
               const float*  __restrict__ w,
               float4*       __restrict__ out4) {
    // Per-cell fold coefficients, fp16: (w00, b=w10-w00, c=w11-w10,
    // g=w00+w11-w01-w10), packed as two half2 = 8 bytes per cell.
    __shared__ __half2 tab[512];
    {
        int t = threadIdx.x;           // cell = i*16 + j
        int v = (t >> 4) * 17 + (t & 15);
        float w00 = w[v], w01 = w[v + 1], w10 = w[v + 17], w11 = w[v + 18];
        tab[2 * t]     = __floats2half2_rn(w00, w10 - w00);
        tab[2 * t + 1] = __floats2half2_rn(w11 - w10, (w00 + w11) - (w01 + w10));
    }
    __syncthreads();

    // Thin thread: 4 points = 2 input float4 (front-batched), 1 output float4.
    int o = blockIdx.x * 256 + threadIdx.x;    // output float4 index

    float4 a0 = x4[2 * o];
    float4 a1 = x4[2 * o + 1];

    float4 r;
    r.x = eval_point(a0.x, a0.y, tab);
    r.y = eval_point(a0.z, a0.w, tab);
    r.z = eval_point(a1.x, a1.y, tab);
    r.w = eval_point(a1.z, a1.w, tab);

    out4[o] = r;
}

extern "C" void kernel_launch(void* const* d_in, const int* in_sizes, int n_in,
                              void* d_out, int out_size) {
    // Identify inputs by element count: x = largest (4,194,304 floats),
    // weight = 289 floats.
    const float* x = nullptr;
    const float* w = nullptr;
    int max_sz = -1;
    for (int k = 0; k < n_in; k++) {
        if (in_sizes[k] == 289) w = (const float*)d_in[k];
        if (in_sizes[k] > max_sz) { max_sz = in_sizes[k]; x = (const float*)d_in[k]; }
    }

    // 2,097,152 points -> 524,288 output float4 -> 2048 blocks x 256 threads.
    p1_eval_kernel<<<2048, 256>>>((const float4*)x, w, (float4*)d_out);
}

// round 15
// speedup vs baseline: 1.0557x; 1.0197x over previous
#include <cuda_runtime.h>
#include <cuda_bf16.h>
#include <cuda_fp16.h>

// P1 FEM evaluation on a structured 17x17 grid over [0,1]^2.
// Direct cell lookup replaces the reference's 512-triangle scan.
//
// DECISION logic is exact fp32 and bitwise-faithful to the JAX reference
// (validated R4-R14):
//  - x*16 is an exact exponent shift; dx, dy, e = dy-dx are EXACT in fp32.
//  - Reference's 6 triangle conditions collapse to: upper wins iff e > -TOL;
//    algebraic fold val = w00 + b*dx + c*dy - max(e,0)*g with
//    b=w10-w00, c=w11-w10, g=w00+w11-w01-w10 (tie band error <= 1e-10*|g|).
//  - Interior grid-line points output 0 (`dead`); x==0 / y==0 edges survive.
//  - fp16 coefficient table (R14, validated): rel_err 5.04e-4 deterministic
//    (fixed harness seed), threshold 1e-3; decisions stay exact fp32.
//
// R15 change (latency-chain attack; FRND+F2I were ~40 cyc of the per-point
// dependent chain):
//  - floor via round-down add: t = add.rm.f32(ux, 2^23) == 2^23 + floor(ux)
//    EXACTLY for ux in [0,16); fx = t - 2^23 exact; dx = ux - fx exact
//    -> identical decision/value bits, no FRND
//  - cell index from mantissa bits of t: bits(t) = 0x4B000000 | i, so
//    cell = ((tx_bits << 4) | ty_bits) & 0xFF  -- SHF+LOP3, no F2I
//  - config frozen at R14 (thin 4-pt threads, 2048x256, 8 blocks/SM)

__device__ __forceinline__ float add_rm(float a, float b) {
    float r;
    asm("add.rm.f32 %0, %1, %2;" : "=f"(r) : "f"(a), "f"(b));
    return r;
}

__device__ __forceinline__ float eval_point(float X, float Y,
                                            const __half2* __restrict__ tab) {
    const float MAGIC = 8388608.0f;    // 2^23
    float ux = X * 16.0f;              // exact (power-of-2 scale)
    float uy = Y * 16.0f;

    float tx = add_rm(ux, MAGIC);      // == 2^23 + floor(ux), exact
    float ty = add_rm(uy, MAGIC);
    float fx = tx - MAGIC;             // floor(ux), exact
    float fy = ty - MAGIC;

    float dx = ux - fx;                // exact
    float dy = uy - fy;                // exact
    float e  = dy - dx;                // exact

    // Interior grid line -> reference's strict bbox test fails everywhere.
    bool dead = ((dx == 0.0f) && (ux != 0.0f)) || ((dy == 0.0f) && (uy != 0.0f));

    // cell = i*16 + j from the mantissa bits of tx/ty (i,j in [0,15]).
    unsigned cell = ((__float_as_uint(tx) << 4) | __float_as_uint(ty)) & 0xFFu;

    // One LDS.64: {half2(w00,b), half2(c,g)}
    __half2 h01 = tab[2 * cell];
    __half2 h23 = tab[2 * cell + 1];
    float2 wb = __half22float2(h01);   // (w00, b)
    float2 cg = __half22float2(h23);   // (c, g)

    float emax = fmaxf(e, 0.0f);
    float val  = fmaf(wb.y, dx, fmaf(cg.x, dy, wb.x));
    val = fmaf(-emax, cg.y, val);

    return dead ? 0.0f : val;
}

__global__ void __launch_bounds__(256, 8)
p1_eval_kernel(const float4* __restrict__ x4,
               const float*  __restrict__ w,
               float4*       __restrict__ out4) {
    // Per-cell fold coefficients, fp16: (w00, b=w10-w00, c=w11-w10,
    // g=w00+w11-w01-w10), packed as two half2 = 8 bytes per cell.
    __shared__ __half2 tab[512];
    {
        int t = threadIdx.x;           // cell = i*16 + j
        int v = (t >> 4) * 17 + (t & 15);
        float w00 = w[v], w01 = w[v + 1], w10 = w[v + 17], w11 = w[v + 18];
        tab[2 * t]     = __floats2half2_rn(w00, w10 - w00);
        tab[2 * t + 1] = __floats2half2_rn(w11 - w10, (w00 + w11) - (w01 + w10));
    }
    __syncthreads();

    // Thin thread: 4 points = 2 input float4 (front-batched), 1 output float4.
    int o = blockIdx.x * 256 + threadIdx.x;    // output float4 index

    float4 a0 = x4[2 * o];
    float4 a1 = x4[2 * o + 1];

    float4 r;
    r.x = eval_point(a0.x, a0.y, tab);
    r.y = eval_point(a0.z, a0.w, tab);
    r.z = eval_point(a1.x, a1.y, tab);
    r.w = eval_point(a1.z, a1.w, tab);

    out4[o] = r;
}

extern "C" void kernel_launch(void* const* d_in, const int* in_sizes, int n_in,
                              void* d_out, int out_size) {
    // Identify inputs by element count: x = largest (4,194,304 floats),
    // weight = 289 floats.
    const float* x = nullptr;
    const float* w = nullptr;
    int max_sz = -1;
    for (int k = 0; k < n_in; k++) {
        if (in_sizes[k] == 289) w = (const float*)d_in[k];
        if (in_sizes[k] > max_sz) { max_sz = in_sizes[k]; x = (const float*)d_in[k]; }
    }

    // 2,097,152 points -> 524,288 output float4 -> 2048 blocks x 256 threads.
    p1_eval_kernel<<<2048, 256>>>((const float4*)x, w, (float4*)d_out);
}